// round 8
// baseline (speedup 1.0000x reference)
#include <cuda_runtime.h>
#include <cuda_bf16.h>

// ---------------- problem constants ----------------
#define BB 8
#define NN 131072
#define SS 1024
#define KK 64
#define CC 32
#define HH 64          // 2*C
#define D1 38          // C + 6
#define D2 70          // H + 6
#define H3 256         // 4*H

#define QPB 4          // queries per block (stage1/2)

// output layout (flattened concat of the 4 returned tensors)
#define OFF_LOCS  0
#define OFF_OUT   (BB*SS*3)                  // 24576
#define OFF_BOXES (OFF_OUT + BB*HH*SS)       // 548864
#define OFF_INDS  (OFF_BOXES + BB*SS*6)      // 598016

typedef unsigned long long ull;

// ---------------- f32x2 packed helpers (sm_100+) ----------------
__device__ __forceinline__ ull pack2(float lo, float hi) {
    ull r; asm("mov.b64 %0, {%1, %2};" : "=l"(r) : "f"(lo), "f"(hi)); return r;
}
__device__ __forceinline__ void unpack2(ull v, float& lo, float& hi) {
    asm("mov.b64 {%0, %1}, %2;" : "=f"(lo), "=f"(hi) : "l"(v));
}
__device__ __forceinline__ void fma2(ull& d, ull a, ull b) {
    asm("fma.rn.f32x2 %0, %1, %2, %0;" : "+l"(d) : "l"(a), "l"(b));
}

// ---------------- scratch (device globals; no allocation allowed) ----------
__device__ float g_feats_nc[BB * NN * CC];   // [B,N,C] transposed feats
__device__ float g_dimbox  [BB * NN * 3];
__device__ float g_fps_locs[BB * SS * 3];
__device__ float g_fps_dim [BB * SS * 3];
__device__ float g_newfeat [BB * SS * HH];   // stage1 output == identity
__device__ float g_h2max   [BB * SS * HH];   // stage2 output

// ---------------- prep: transpose feats, compute dim boxes ----------------
__global__ __launch_bounds__(256) void prep_kernel(
    const float* __restrict__ feats, const float* __restrict__ boxes)
{
    int idx = blockIdx.x * blockDim.x + threadIdx.x;   // over B*N
    if (idx >= BB * NN) return;
    int b = idx >> 17;
    int n = idx & (NN - 1);

    float tmp[CC];
    #pragma unroll
    for (int c = 0; c < CC; c++)
        tmp[c] = feats[(b * CC + c) * NN + n];

    float4* dst = (float4*)(g_feats_nc + ((size_t)idx << 5));
    #pragma unroll
    for (int q = 0; q < 8; q++)
        dst[q] = make_float4(tmp[4*q], tmp[4*q+1], tmp[4*q+2], tmp[4*q+3]);

    const float* bx = boxes + (size_t)idx * 6;
    float* dd = g_dimbox + (size_t)idx * 3;
    dd[0] = bx[3] - bx[0];
    dd[1] = bx[4] - bx[1];
    dd[2] = bx[5] - bx[2];
}

// ---------------- fps gather ----------
__global__ __launch_bounds__(256) void fps_kernel(
    const float* __restrict__ locs, const float* __restrict__ boxes,
    const int* __restrict__ fps_inds, float* __restrict__ out)
{
    int idx = blockIdx.x * blockDim.x + threadIdx.x;   // over B*S
    if (idx >= BB * SS) return;
    int b = idx >> 10;
    int j = fps_inds[idx];

    const float* lp = locs + ((size_t)b * NN + j) * 3;
    float l0 = lp[0], l1 = lp[1], l2 = lp[2];
    g_fps_locs[idx*3+0] = l0; g_fps_locs[idx*3+1] = l1; g_fps_locs[idx*3+2] = l2;
    out[OFF_LOCS + idx*3 + 0] = l0;
    out[OFF_LOCS + idx*3 + 1] = l1;
    out[OFF_LOCS + idx*3 + 2] = l2;

    const float* bx = boxes + ((size_t)b * NN + j) * 6;
    float b0 = bx[0], b1 = bx[1], b2 = bx[2], b3 = bx[3], b4 = bx[4], b5 = bx[5];
    g_fps_dim[idx*3+0] = b3 - b0;
    g_fps_dim[idx*3+1] = b4 - b1;
    g_fps_dim[idx*3+2] = b5 - b2;
    out[OFF_BOXES + idx*6 + 0] = b0;
    out[OFF_BOXES + idx*6 + 1] = b1;
    out[OFF_BOXES + idx*6 + 2] = b2;
    out[OFF_BOXES + idx*6 + 3] = b3;
    out[OFF_BOXES + idx*6 + 4] = b4;
    out[OFF_BOXES + idx*6 + 5] = b5;

    out[OFF_INDS + idx] = (float)j;
}

// splat-w interleave slots (ull index within one i-row)
// 64-ch case: chunk16B = ((c&7)>>1)*8 + (c>>3); ull = chunk*2 + (c&1)
__device__ __forceinline__ int slot64(int c) {
    return ((((c & 7) >> 1) * 8 + (c >> 3)) << 1) | (c & 1);
}
// 32-ch case: chunk16B = ((c&3)>>1)*8 + (c>>2); ull = chunk*2 + (c&1)
__device__ __forceinline__ int slot32(int c) {
    return ((((c & 3) >> 1) * 8 + (c >> 2)) << 1) | (c & 1);
}

// ================= stage 1 =================
// smem floats: wa_splat[2432] wb_splat[4096] ba[32] bb[64] | per-q: g1[2432] h1[2176]
#define S1_BASE (D1*CC*2 + CC*HH*2 + CC + HH)     // 6624
#define S1_PERQ (D1*64 + CC*68)                   // 4608
#define S1_SMEM ((S1_BASE + QPB*S1_PERQ) * 4)     // 100224 bytes

__global__ __launch_bounds__(64*QPB, 2) void stage1_kernel(
    const float* __restrict__ locs, const int* __restrict__ nbr,
    const float* __restrict__ w1a, const float* __restrict__ s1a, const float* __restrict__ t1a,
    const float* __restrict__ w1b, const float* __restrict__ s1b, const float* __restrict__ t1b)
{
    extern __shared__ float sm[];
    ull*   wau  = (ull*)sm;                       // D1*CC ull
    ull*   wbu  = (ull*)(sm + D1*CC*2);           // CC*HH ull
    float* ba_s = sm + D1*CC*2 + CC*HH*2;         // CC
    float* bb_s = ba_s + CC;                      // HH
    int tid  = threadIdx.x;
    int q    = tid >> 6;
    int ltid = tid & 63;
    float* g1_s = sm + S1_BASE + q * S1_PERQ;     // D1*64
    float* h1_s = g1_s + D1*64;                   // CC*68
    float* red  = g1_s;                           // overlay (g1 dead after GEMM A)

    int bs = blockIdx.x * QPB + q;
    int b  = bs >> 10;

    // fold + splat + interleave weights
    for (int idx = tid; idx < D1 * CC; idx += 64*QPB) {
        int i = idx >> 5, c = idx & 31;
        float v = w1a[idx] * s1a[c];
        wau[i * 32 + slot32(c)] = pack2(v, v);
    }
    for (int idx = tid; idx < CC * HH; idx += 64*QPB) {
        int i = idx >> 6, c = idx & 63;
        float v = w1b[idx] * s1b[c];
        wbu[i * 64 + slot64(c)] = pack2(v, v);
    }
    if (tid < CC) ba_s[tid] = t1a[tid];
    if (tid < HH) bb_s[tid] = t1b[tid];

    // ---- fill g1_s[i][n]: thread = neighbor ----
    {
        int j = nbr[bs * KK + ltid];
        const float* lp = locs + ((size_t)b * NN + j) * 3;
        g1_s[0*64 + ltid] = (lp[0] - g_fps_locs[bs*3+0]) * 2.5f;
        g1_s[1*64 + ltid] = (lp[1] - g_fps_locs[bs*3+1]) * 2.5f;
        g1_s[2*64 + ltid] = (lp[2] - g_fps_locs[bs*3+2]) * 2.5f;
        const float* dp = g_dimbox + ((size_t)b * NN + j) * 3;
        g1_s[3*64 + ltid] = fabsf(dp[0] - g_fps_dim[bs*3+0]);
        g1_s[4*64 + ltid] = fabsf(dp[1] - g_fps_dim[bs*3+1]);
        g1_s[5*64 + ltid] = fabsf(dp[2] - g_fps_dim[bs*3+2]);
        const float4* fp = (const float4*)(g_feats_nc + (((size_t)b * NN + j) << 5));
        #pragma unroll
        for (int qq = 0; qq < 8; qq++) {
            float4 v = fp[qq];
            g1_s[(6+4*qq+0)*64 + ltid] = v.x;
            g1_s[(6+4*qq+1)*64 + ltid] = v.y;
            g1_s[(6+4*qq+2)*64 + ltid] = v.z;
            g1_s[(6+4*qq+3)*64 + ltid] = v.w;
        }
    }
    __syncthreads();

    int cgrp = ltid & 7, ngrp = ltid >> 3;   // phase-mates share ngrp -> g broadcast
    int n0 = ngrp * 8;

    // ---- GEMM A: 38 -> 32, relu. acc[nbr-pair][channel], 4x4. ----
    {
        int c0 = cgrp * 4;
        const ulonglong2* w16 = (const ulonglong2*)wau;
        ull acc[4][4];
        #pragma unroll
        for (int cc = 0; cc < 4; cc++) {
            ull bi = pack2(ba_s[c0+cc], ba_s[c0+cc]);
            #pragma unroll
            for (int p = 0; p < 4; p++) acc[p][cc] = bi;
        }
        #pragma unroll 2
        for (int i = 0; i < D1; i++) {
            ulonglong2 ga = *(const ulonglong2*)(g1_s + i * 64 + n0);
            ulonglong2 gb = *(const ulonglong2*)(g1_s + i * 64 + n0 + 4);
            ull gp[4] = { ga.x, ga.y, gb.x, gb.y };
            ulonglong2 w0 = w16[i*16 + 0*8 + cgrp];   // channels c0+0,c0+1 splatted
            ulonglong2 w1 = w16[i*16 + 1*8 + cgrp];   // channels c0+2,c0+3
            ull wc[4] = { w0.x, w0.y, w1.x, w1.y };
            #pragma unroll
            for (int p = 0; p < 4; p++)
                #pragma unroll
                for (int cc = 0; cc < 4; cc++) fma2(acc[p][cc], gp[p], wc[cc]);
        }
        // relu + store pairs to h1_s[c][n]
        #pragma unroll
        for (int cc = 0; cc < 4; cc++)
            #pragma unroll
            for (int p = 0; p < 4; p++) {
                float lo, hi; unpack2(acc[p][cc], lo, hi);
                ull v = pack2(fmaxf(lo, 0.0f), fmaxf(hi, 0.0f));
                *(ull*)(h1_s + (c0+cc)*68 + n0 + 2*p) = v;
            }
    }
    __syncthreads();

    // ---- GEMM B: 32 -> 64, relu, max over K. acc 4x8. ----
    {
        int c0 = cgrp * 8;
        const ulonglong2* w16 = (const ulonglong2*)wbu;
        ull acc[4][8];
        #pragma unroll
        for (int cc = 0; cc < 8; cc++) {
            ull bi = pack2(bb_s[c0+cc], bb_s[c0+cc]);
            #pragma unroll
            for (int p = 0; p < 4; p++) acc[p][cc] = bi;
        }
        #pragma unroll 2
        for (int i = 0; i < CC; i++) {
            ulonglong2 ga = *(const ulonglong2*)(h1_s + i * 68 + n0);
            ulonglong2 gb = *(const ulonglong2*)(h1_s + i * 68 + n0 + 4);
            ull gp[4] = { ga.x, ga.y, gb.x, gb.y };
            ulonglong2 w0 = w16[i*32 + 0*8 + cgrp];
            ulonglong2 w1 = w16[i*32 + 1*8 + cgrp];
            ulonglong2 w2v = w16[i*32 + 2*8 + cgrp];
            ulonglong2 w3 = w16[i*32 + 3*8 + cgrp];
            ull wc[8] = { w0.x, w0.y, w1.x, w1.y, w2v.x, w2v.y, w3.x, w3.y };
            #pragma unroll
            for (int p = 0; p < 4; p++)
                #pragma unroll
                for (int cc = 0; cc < 8; cc++) fma2(acc[p][cc], gp[p], wc[cc]);
        }
        // max over 8 local neighbors (relu deferred: monotone)
        float m[8];
        #pragma unroll
        for (int cc = 0; cc < 8; cc++) {
            float lo, hi; unpack2(acc[0][cc], lo, hi);
            m[cc] = fmaxf(lo, hi);
            #pragma unroll
            for (int p = 1; p < 4; p++) {
                unpack2(acc[p][cc], lo, hi);
                m[cc] = fmaxf(m[cc], fmaxf(lo, hi));
            }
        }
        __syncthreads();   // before red overlays g1_s
        #pragma unroll
        for (int cc = 0; cc < 8; cc++) red[ngrp * 68 + c0 + cc] = m[cc];
    }
    __syncthreads();

    float mm = red[ltid];
    #pragma unroll
    for (int r = 1; r < 8; r++) mm = fmaxf(mm, red[r * 68 + ltid]);
    g_newfeat[bs * HH + ltid] = fmaxf(mm, 0.0f);
}

// ================= stage 2 =================
// smem floats: w_splat[8960] sb[64] | per-q: g[4480]
#define S2_BASE (D2*HH*2 + HH)                    // 9024
#define S2_PERQ (D2*64)                           // 4480
#define S2_SMEM ((S2_BASE + QPB*S2_PERQ) * 4)     // 107776 bytes

__global__ __launch_bounds__(64*QPB, 2) void stage2_kernel(
    const int* __restrict__ nbr2,
    const float* __restrict__ w2, const float* __restrict__ s2, const float* __restrict__ t2)
{
    extern __shared__ float sm[];
    ull*   w2u = (ull*)sm;                        // D2*HH ull
    float* sb  = sm + D2*HH*2;                    // HH
    int tid  = threadIdx.x;
    int q    = tid >> 6;
    int ltid = tid & 63;
    float* g_s = sm + S2_BASE + q * S2_PERQ;      // D2*64
    float* red = g_s;                             // overlay after compute

    int bs = blockIdx.x * QPB + q;
    int b  = bs >> 10;

    for (int idx = tid; idx < D2 * HH; idx += 64*QPB) {
        int i = idx >> 6, c = idx & 63;
        float v = w2[idx] * s2[c];
        w2u[i * 64 + slot64(c)] = pack2(v, v);
    }
    if (tid < HH) sb[tid] = t2[tid];

    // ---- fill g_s[i][n]: thread = neighbor ----
    {
        int j  = nbr2[bs * KK + ltid];
        int fj = (b << 10) + j;
        g_s[0*64 + ltid] = (g_fps_locs[fj*3+0] - g_fps_locs[bs*3+0]) * 1.25f;
        g_s[1*64 + ltid] = (g_fps_locs[fj*3+1] - g_fps_locs[bs*3+1]) * 1.25f;
        g_s[2*64 + ltid] = (g_fps_locs[fj*3+2] - g_fps_locs[bs*3+2]) * 1.25f;
        g_s[3*64 + ltid] = fabsf(g_fps_dim[fj*3+0] - g_fps_dim[bs*3+0]);
        g_s[4*64 + ltid] = fabsf(g_fps_dim[fj*3+1] - g_fps_dim[bs*3+1]);
        g_s[5*64 + ltid] = fabsf(g_fps_dim[fj*3+2] - g_fps_dim[bs*3+2]);
        const float4* fp = (const float4*)(g_newfeat + (size_t)fj * HH);
        #pragma unroll
        for (int qq = 0; qq < 16; qq++) {
            float4 v = fp[qq];
            g_s[(6+4*qq+0)*64 + ltid] = v.x;
            g_s[(6+4*qq+1)*64 + ltid] = v.y;
            g_s[(6+4*qq+2)*64 + ltid] = v.z;
            g_s[(6+4*qq+3)*64 + ltid] = v.w;
        }
    }
    __syncthreads();

    int cgrp = ltid & 7, ngrp = ltid >> 3;
    int n0 = ngrp * 8, c0 = cgrp * 8;

    const ulonglong2* w16 = (const ulonglong2*)w2u;
    ull acc[4][8];
    #pragma unroll
    for (int cc = 0; cc < 8; cc++) {
        ull bi = pack2(sb[c0+cc], sb[c0+cc]);
        #pragma unroll
        for (int p = 0; p < 4; p++) acc[p][cc] = bi;
    }

    #pragma unroll 2
    for (int i = 0; i < D2; i++) {
        ulonglong2 ga = *(const ulonglong2*)(g_s + i * 64 + n0);
        ulonglong2 gb = *(const ulonglong2*)(g_s + i * 64 + n0 + 4);
        ull gp[4] = { ga.x, ga.y, gb.x, gb.y };
        ulonglong2 w0 = w16[i*32 + 0*8 + cgrp];
        ulonglong2 w1 = w16[i*32 + 1*8 + cgrp];
        ulonglong2 w2v = w16[i*32 + 2*8 + cgrp];
        ulonglong2 w3 = w16[i*32 + 3*8 + cgrp];
        ull wc[8] = { w0.x, w0.y, w1.x, w1.y, w2v.x, w2v.y, w3.x, w3.y };
        #pragma unroll
        for (int p = 0; p < 4; p++)
            #pragma unroll
            for (int cc = 0; cc < 8; cc++) fma2(acc[p][cc], gp[p], wc[cc]);
    }

    // max over 8 local neighbors (no relu in stage 2)
    float m[8];
    #pragma unroll
    for (int cc = 0; cc < 8; cc++) {
        float lo, hi; unpack2(acc[0][cc], lo, hi);
        m[cc] = fmaxf(lo, hi);
        #pragma unroll
        for (int p = 1; p < 4; p++) {
            unpack2(acc[p][cc], lo, hi);
            m[cc] = fmaxf(m[cc], fmaxf(lo, hi));
        }
    }
    __syncthreads();   // before red overlays g_s
    #pragma unroll
    for (int cc = 0; cc < 8; cc++) red[ngrp * 68 + c0 + cc] = m[cc];
    __syncthreads();

    float mm = red[ltid];
    #pragma unroll
    for (int r = 1; r < 8; r++) mm = fmaxf(mm, red[r * 68 + ltid]);
    g_h2max[bs * HH + ltid] = mm;
}

// ---------------- stage 3: bottleneck mlp3 + skip, write transposed ------
#define TS 16
__global__ __launch_bounds__(256) void stage3_kernel(
    const float* __restrict__ w3a, const float* __restrict__ s3a, const float* __restrict__ t3a,
    const float* __restrict__ w3b, const float* __restrict__ s3b, const float* __restrict__ t3b,
    float* __restrict__ out)
{
    __shared__ float h2s[TS * HH];
    __shared__ float h3s[TS * H3];
    int t = threadIdx.x;
    int row0 = blockIdx.x * TS;

    for (int i = t; i < TS * HH; i += 256) h2s[i] = g_h2max[row0 * HH + i];
    __syncthreads();

    {
        float sc = s3a[t], bi = t3a[t];
        float acc[TS];
        #pragma unroll
        for (int r = 0; r < TS; r++) acc[r] = bi;
        #pragma unroll 4
        for (int i = 0; i < HH; i++) {
            float wv = w3a[i * H3 + t] * sc;
            #pragma unroll
            for (int r = 0; r < TS; r++) acc[r] += h2s[r * HH + i] * wv;
        }
        #pragma unroll
        for (int r = 0; r < TS; r++) h3s[r * H3 + t] = fmaxf(acc[r], 0.0f);
    }
    __syncthreads();

    {
        int c  = t & 63;
        int rg = t >> 6;
        float sc = s3b[c], bi = t3b[c];
        float acc[4];
        #pragma unroll
        for (int rr = 0; rr < 4; rr++) acc[rr] = bi;
        #pragma unroll 4
        for (int i = 0; i < H3; i++) {
            float wv = w3b[i * HH + c] * sc;
            #pragma unroll
            for (int rr = 0; rr < 4; rr++)
                acc[rr] += h3s[(rg * 4 + rr) * H3 + i] * wv;
        }
        #pragma unroll
        for (int rr = 0; rr < 4; rr++) {
            int row = row0 + rg * 4 + rr;
            int b = row >> 10, s = row & 1023;
            float v = acc[rr] + g_newfeat[row * HH + c];
            out[OFF_OUT + ((b * HH + c) << 10) + s] = fmaxf(v, 0.0f);
        }
    }
}

// ---------------- launch ----------------
extern "C" void kernel_launch(void* const* d_in, const int* in_sizes, int n_in,
                              void* d_out, int out_size)
{
    const float* locs  = (const float*)d_in[0];
    const float* feats = (const float*)d_in[1];
    const float* boxes = (const float*)d_in[2];
    const int*   fps   = (const int*)d_in[3];
    const int*   nbr   = (const int*)d_in[4];
    const int*   nbr2  = (const int*)d_in[5];
    const float* w1a = (const float*)d_in[6];
    const float* s1a = (const float*)d_in[7];
    const float* t1a = (const float*)d_in[8];
    const float* w1b = (const float*)d_in[9];
    const float* s1b = (const float*)d_in[10];
    const float* t1b = (const float*)d_in[11];
    const float* w2  = (const float*)d_in[12];
    const float* s2  = (const float*)d_in[13];
    const float* t2  = (const float*)d_in[14];
    const float* w3a = (const float*)d_in[15];
    const float* s3a = (const float*)d_in[16];
    const float* t3a = (const float*)d_in[17];
    const float* w3b = (const float*)d_in[18];
    const float* s3b = (const float*)d_in[19];
    const float* t3b = (const float*)d_in[20];
    float* out = (float*)d_out;

    cudaFuncSetAttribute(stage1_kernel, cudaFuncAttributeMaxDynamicSharedMemorySize, S1_SMEM);
    cudaFuncSetAttribute(stage2_kernel, cudaFuncAttributeMaxDynamicSharedMemorySize, S2_SMEM);

    prep_kernel<<<(BB * NN + 255) / 256, 256>>>(feats, boxes);
    fps_kernel<<<(BB * SS + 255) / 256, 256>>>(locs, boxes, fps, out);
    stage1_kernel<<<BB * SS / QPB, 64*QPB, S1_SMEM>>>(locs, nbr, w1a, s1a, t1a, w1b, s1b, t1b);
    stage2_kernel<<<BB * SS / QPB, 64*QPB, S2_SMEM>>>(nbr2, w2, s2, t2);
    stage3_kernel<<<(BB * SS) / TS, 256>>>(w3a, s3a, t3a, w3b, s3b, t3b, out);
}